// round 9
// baseline (speedup 1.0000x reference)
#include <cuda_runtime.h>

// RGCN constants
constexpr int N_   = 50000;
constexpr int E_   = 500000;
constexpr int R_   = 20;
constexpr int RT_  = 41;            // 2R+1
constexpr int B_   = 40;
constexpr int EMB_ = 16;
constexpr int C_   = 16;
constexpr int NE_  = N_ * EMB_;     // 800000
constexpr int RC_  = RT_ * C_;      // 656
constexpr int JP_  = NE_ / 2;       // 400000 j-pairs
constexpr int WBn  = JP_ / 128;     // 3125 w1 blocks (256 thr = 128 jp each)
constexpr int CBn  = (E_ + 255) / 256;   // count blocks

// Scratch (static device globals)
__device__ float g_w1[(size_t)RT_ * NE_];   // [41][50000][16]
__device__ float g_h[NE_];                  // layer-1 activations (post-relu after k_relu)
__device__ int   g_cnt[RT_ * N_];           // per-(r,s) edge counts
__device__ float g_w2f[EMB_ * RC_];         // w2 flat [e][r*16+c]

// ---------------------------------------------------------------------------
// pre-pass: zero cnt & h, seed out with bias2, compute w2f. One launch.
__global__ void k_pre(float* __restrict__ out, const float* __restrict__ bias2,
                      const float* __restrict__ comps2,
                      const float* __restrict__ bases2) {
    int i = blockIdx.x * blockDim.x + threadIdx.x;
    if (i < RT_ * N_) g_cnt[i] = 0;
    if (i < NE_) { g_h[i] = 0.0f; out[i] = bias2[i & 15]; }
    if (i < RT_ * EMB_ * C_) {
        int r = i >> 8, ec = i & 255;
        int e = ec >> 4, c = ec & 15;
        float acc = 0.0f;
#pragma unroll
        for (int b = 0; b < B_; b++)
            acc = fmaf(comps2[r * B_ + b], bases2[b * 256 + ec], acc);
        g_w2f[e * RC_ + r * 16 + c] = acc;
    }
}

// ---------------------------------------------------------------------------
// Fused w1-GEMM + edge counting.
// w1: lane-PAIR per j-pair. Even lane: b=0..19, odd lane: b=20..39 (20 f32x2
// bases = 40 regs, no spill). comps quad-packed {c2k,c2k,c2k+1,c2k+1} in smem:
// one LDS.128 feeds two FFMA2. Combine halves with one 64-bit shfl + f32x2 add.
__global__ void __launch_bounds__(256) k_w1c(const float* __restrict__ comps1,
                                             const float* __restrict__ bases1,
                                             const int* __restrict__ src,
                                             const int* __restrict__ dst,
                                             const int* __restrict__ rel) {
    if (blockIdx.x >= WBn) {
        int i = (blockIdx.x - WBn) * 256 + threadIdx.x;
        if (i < E_) {
            int r = rel[i];
            atomicAdd(&g_cnt[r * N_ + src[i]], 1);
            atomicAdd(&g_cnt[(r + R_) * N_ + dst[i]], 1);
        }
        return;
    }

    // quads: [r][k], k=0..19, quad k = bases-pair (b=2k, 2k+1), each dup'd {c,c}
    __shared__ __align__(16) ulonglong2 cs4[RT_ * 20];
    for (int t = threadIdx.x; t < RT_ * 20; t += 256) {
        int r = t / 20, k = t % 20;
        unsigned int ca = __float_as_uint(comps1[r * B_ + 2 * k]);
        unsigned int cb = __float_as_uint(comps1[r * B_ + 2 * k + 1]);
        ulonglong2 q;
        asm("mov.b64 %0, {%1, %1};" : "=l"(q.x) : "r"(ca));
        asm("mov.b64 %0, {%1, %1};" : "=l"(q.y) : "r"(cb));
        cs4[t] = q;
    }
    __syncthreads();

    int half = threadIdx.x & 1;                     // which b-half this lane owns
    int jp   = blockIdx.x * 128 + (threadIdx.x >> 1);

    unsigned long long bp[20];                      // 20 x float2 = 40 regs
#pragma unroll
    for (int k = 0; k < 20; k++)
        bp[k] = *(const unsigned long long*)
                 &bases1[(size_t)(half * 20 + k) * NE_ + 2 * jp];

    int kbase = half * 10;                          // quad offset for this half
#pragma unroll 1
    for (int r = 0; r < RT_; r++) {
        const ulonglong2* cq = &cs4[r * 20 + kbase];
        unsigned long long acc = 0ull;
#pragma unroll
        for (int k = 0; k < 10; k++) {
            ulonglong2 q = cq[k];                   // LDS.128 -> 2 comps pairs
            asm("fma.rn.f32x2 %0, %1, %2, %0;" : "+l"(acc) : "l"(bp[2*k]),   "l"(q.x));
            asm("fma.rn.f32x2 %0, %1, %2, %0;" : "+l"(acc) : "l"(bp[2*k+1]), "l"(q.y));
        }
        unsigned long long other = __shfl_xor_sync(0xffffffffu, acc, 1);
        asm("add.rn.f32x2 %0, %0, %1;" : "+l"(acc) : "l"(other));
        if (!half)
            *(unsigned long long*)&g_w1[(size_t)r * NE_ + 2 * jp] = acc;
    }
}

// ---------------------------------------------------------------------------
// layer-1 scatter: h[s,:] += v * w1[r, o, :].  4 threads/edge, one RED.v4 each.
__global__ void k_l1(const int* __restrict__ src, const int* __restrict__ dst,
                     const int* __restrict__ rel) {
    int idx = blockIdx.x * blockDim.x + threadIdx.x;
    if (idx >= 2 * E_ * 4) return;
    int q  = idx & 3;
    int e2 = idx >> 2;
    int s, o, r;
    if (e2 < E_) { s = src[e2]; o = dst[e2]; r = rel[e2]; }
    else         { int e = e2 - E_; s = dst[e]; o = src[e]; r = rel[e] + R_; }
    float v = 1.0f / (float)g_cnt[r * N_ + s];
    const float4 w = *(const float4*)&g_w1[(size_t)r * NE_ + o * EMB_ + q * 4];
    float* hp = &g_h[s * EMB_ + q * 4];
    asm volatile("red.global.add.v4.f32 [%0], {%1, %2, %3, %4};"
                 :: "l"(hp), "f"(v * w.x), "f"(v * w.y), "f"(v * w.z), "f"(v * w.w)
                 : "memory");
}

// self-loop (v=1) + bias + relu  (h must be final before k_l2f)
__global__ void k_relu(const float* __restrict__ bias1) {
    int j = blockIdx.x * blockDim.x + threadIdx.x;
    if (j >= NE_) return;
    float x = g_h[j] + g_w1[(size_t)(RT_ - 1) * NE_ + j] + bias1[j & 15];
    g_h[j] = fmaxf(x, 0.0f);
}

// ---------------------------------------------------------------------------
// Fused layer-2: out[s, q4] += v * sum_e h[o,e] * w2f[e][r*16+q4]
// 4 lanes per edge (lane = q, quarter of the 16 output classes).
// h row (64B) loaded coalesced once per edge, spread via width-4 shfl.
// w2 in smem (42KB). Self-loop pseudo-edges (r=40, v=1) included; bias2
// pre-seeded into out by k_pre. No g_m scratch at all.
__global__ void __launch_bounds__(256) k_l2f(const int* __restrict__ src,
                                             const int* __restrict__ dst,
                                             const int* __restrict__ rel,
                                             float* __restrict__ out) {
    __shared__ float w2s[EMB_ * RC_];               // 41984 B
    for (int t = threadIdx.x; t < EMB_ * RC_; t += 256) w2s[t] = g_w2f[t];
    __syncthreads();

    int idx = blockIdx.x * 256 + threadIdx.x;
    if (idx >= (2 * E_ + N_) * 4) return;
    int q  = idx & 3;
    int e2 = idx >> 2;

    int s, o, r;
    float v;
    if (e2 < E_) {
        s = src[e2]; o = dst[e2]; r = rel[e2];
        v = 1.0f / (float)g_cnt[r * N_ + s];
    } else if (e2 < 2 * E_) {
        int e = e2 - E_;
        s = dst[e]; o = src[e]; r = rel[e] + R_;
        v = 1.0f / (float)g_cnt[r * N_ + s];
    } else {
        int n = e2 - 2 * E_;
        s = n; o = n; r = RT_ - 1; v = 1.0f;
    }

    const float4 hq = *(const float4*)&g_h[o * EMB_ + q * 4];  // my quarter
    const float* wbase = &w2s[r * 16 + q * 4];
    float4 acc = make_float4(0.f, 0.f, 0.f, 0.f);
#pragma unroll
    for (int t = 0; t < 4; t++) {
        // h[o][4t..4t+3] from lane t of this edge's 4-lane group
        float4 ht;
        ht.x = __shfl_sync(0xffffffffu, hq.x, t, 4);
        ht.y = __shfl_sync(0xffffffffu, hq.y, t, 4);
        ht.z = __shfl_sync(0xffffffffu, hq.z, t, 4);
        ht.w = __shfl_sync(0xffffffffu, hq.w, t, 4);
        float4 w0 = *(const float4*)&wbase[(4 * t + 0) * RC_];
        float4 w1v = *(const float4*)&wbase[(4 * t + 1) * RC_];
        float4 w2v = *(const float4*)&wbase[(4 * t + 2) * RC_];
        float4 w3 = *(const float4*)&wbase[(4 * t + 3) * RC_];
        acc.x = fmaf(ht.x, w0.x, acc.x); acc.y = fmaf(ht.x, w0.y, acc.y);
        acc.z = fmaf(ht.x, w0.z, acc.z); acc.w = fmaf(ht.x, w0.w, acc.w);
        acc.x = fmaf(ht.y, w1v.x, acc.x); acc.y = fmaf(ht.y, w1v.y, acc.y);
        acc.z = fmaf(ht.y, w1v.z, acc.z); acc.w = fmaf(ht.y, w1v.w, acc.w);
        acc.x = fmaf(ht.z, w2v.x, acc.x); acc.y = fmaf(ht.z, w2v.y, acc.y);
        acc.z = fmaf(ht.z, w2v.z, acc.z); acc.w = fmaf(ht.z, w2v.w, acc.w);
        acc.x = fmaf(ht.w, w3.x, acc.x); acc.y = fmaf(ht.w, w3.y, acc.y);
        acc.z = fmaf(ht.w, w3.z, acc.z); acc.w = fmaf(ht.w, w3.w, acc.w);
    }
    float* op = &out[s * C_ + q * 4];
    asm volatile("red.global.add.v4.f32 [%0], {%1, %2, %3, %4};"
                 :: "l"(op), "f"(v * acc.x), "f"(v * acc.y),
                    "f"(v * acc.z), "f"(v * acc.w)
                 : "memory");
}

// ---------------------------------------------------------------------------
extern "C" void kernel_launch(void* const* d_in, const int* in_sizes, int n_in,
                              void* d_out, int out_size) {
    const int*   src    = (const int*)d_in[0];
    const int*   dst    = (const int*)d_in[1];
    const int*   rel    = (const int*)d_in[2];
    const float* comps1 = (const float*)d_in[3];
    const float* bases1 = (const float*)d_in[4];
    const float* comps2 = (const float*)d_in[5];
    const float* bases2 = (const float*)d_in[6];
    const float* bias1  = (const float*)d_in[7];
    const float* bias2  = (const float*)d_in[8];
    float* out = (float*)d_out;

    const int T = 256;
    k_pre  <<<(RT_ * N_ + T - 1) / T, T>>>(out, bias2, comps2, bases2);
    k_w1c  <<<WBn + CBn, T>>>(comps1, bases1, src, dst, rel);
    k_l1   <<<(2 * E_ * 4 + T - 1) / T, T>>>(src, dst, rel);
    k_relu <<<(NE_ + T - 1) / T, T>>>(bias1);
    k_l2f  <<<((2 * E_ + N_) * 4 + T - 1) / T, T>>>(src, dst, rel, out);
}

// round 10
// speedup vs baseline: 1.1677x; 1.1677x over previous
#include <cuda_runtime.h>

// RGCN constants
constexpr int N_   = 50000;
constexpr int E_   = 500000;
constexpr int R_   = 20;
constexpr int RT_  = 41;            // 2R+1
constexpr int B_   = 40;
constexpr int EMB_ = 16;
constexpr int C_   = 16;
constexpr int NE_  = N_ * EMB_;     // 800000
constexpr int RC_  = RT_ * C_;      // 656
constexpr int CH_  = RC_ / 4;       // 164 float4 chunks
constexpr int JP_  = NE_ / 2;       // 400000 j-pairs
constexpr int WBn  = JP_ / 128;     // 3125 w1 blocks (256 thr, lane-pairs)
constexpr int CBn  = (E_ + 255) / 256;   // count blocks

// Scratch (static device globals)
__device__ float g_w1[(size_t)RT_ * NE_];   // [41][50000][16]
__device__ float g_h[NE_];                  // layer-1 pre-activations
__device__ int   g_cnt[RT_ * N_];           // per-(r,s) edge counts
__device__ float g_w2f[EMB_ * RC_];         // w2 flat [e][r*16+c]
__device__ float g_m[(size_t)N_ * RC_];     // m[o][r][c]  ~131 MB

// ---------------------------------------------------------------------------
// pre-pass: zero cnt & h, seed out with bias2, compute w2f. One launch.
__global__ void k_pre(float* __restrict__ out, const float* __restrict__ bias2,
                      const float* __restrict__ comps2,
                      const float* __restrict__ bases2) {
    int i = blockIdx.x * blockDim.x + threadIdx.x;
    if (i < RT_ * N_) g_cnt[i] = 0;
    if (i < NE_) { g_h[i] = 0.0f; out[i] = bias2[i & 15]; }
    if (i < RT_ * EMB_ * C_) {
        int r = i >> 8, ec = i & 255;
        int e = ec >> 4, c = ec & 15;
        float acc = 0.0f;
#pragma unroll
        for (int b = 0; b < B_; b++)
            acc = fmaf(comps2[r * B_ + b], bases2[b * 256 + ec], acc);
        g_w2f[e * RC_ + r * 16 + c] = acc;
    }
}

// ---------------------------------------------------------------------------
// Fused w1-GEMM + edge counting.
// Lane-PAIR per j-pair: even lane b=0..19, odd b=20..39 -> bp[20]=40 regs,
// no spill. comps quad-packed {c2k,c2k,c2k+1,c2k+1}; LDS.128 feeds 2 FFMA2.
// Halves combined with one 64-bit shfl + f32x2 add; even lane stores.
__global__ void __launch_bounds__(256) k_w1c(const float* __restrict__ comps1,
                                             const float* __restrict__ bases1,
                                             const int* __restrict__ src,
                                             const int* __restrict__ dst,
                                             const int* __restrict__ rel) {
    if (blockIdx.x >= WBn) {
        int i = (blockIdx.x - WBn) * 256 + threadIdx.x;
        if (i < E_) {
            int r = rel[i];
            atomicAdd(&g_cnt[r * N_ + src[i]], 1);
            atomicAdd(&g_cnt[(r + R_) * N_ + dst[i]], 1);
        }
        return;
    }

    __shared__ __align__(16) ulonglong2 cs4[RT_ * 20];
    for (int t = threadIdx.x; t < RT_ * 20; t += 256) {
        int r = t / 20, k = t % 20;
        unsigned int ca = __float_as_uint(comps1[r * B_ + 2 * k]);
        unsigned int cb = __float_as_uint(comps1[r * B_ + 2 * k + 1]);
        ulonglong2 q;
        asm("mov.b64 %0, {%1, %1};" : "=l"(q.x) : "r"(ca));
        asm("mov.b64 %0, {%1, %1};" : "=l"(q.y) : "r"(cb));
        cs4[t] = q;
    }
    __syncthreads();

    int half = threadIdx.x & 1;
    int jp   = blockIdx.x * 128 + (threadIdx.x >> 1);

    unsigned long long bp[20];                      // 20 x float2 = 40 regs
#pragma unroll
    for (int k = 0; k < 20; k++)
        bp[k] = *(const unsigned long long*)
                 &bases1[(size_t)(half * 20 + k) * NE_ + 2 * jp];

    int kbase = half * 10;
#pragma unroll 1
    for (int r = 0; r < RT_; r++) {
        const ulonglong2* cq = &cs4[r * 20 + kbase];
        unsigned long long acc = 0ull;
#pragma unroll
        for (int k = 0; k < 10; k++) {
            ulonglong2 q = cq[k];
            asm("fma.rn.f32x2 %0, %1, %2, %0;" : "+l"(acc) : "l"(bp[2*k]),   "l"(q.x));
            asm("fma.rn.f32x2 %0, %1, %2, %0;" : "+l"(acc) : "l"(bp[2*k+1]), "l"(q.y));
        }
        unsigned long long other = __shfl_xor_sync(0xffffffffu, acc, 1);
        asm("add.rn.f32x2 %0, %0, %1;" : "+l"(acc) : "l"(other));
        if (!half)
            *(unsigned long long*)&g_w1[(size_t)r * NE_ + 2 * jp] = acc;
    }
}

// ---------------------------------------------------------------------------
// layer-1 scatter: h[s,:] += v * w1[r, o, :].  4 threads/edge, one RED.v4 each.
__global__ void k_l1(const int* __restrict__ src, const int* __restrict__ dst,
                     const int* __restrict__ rel) {
    int idx = blockIdx.x * blockDim.x + threadIdx.x;
    if (idx >= 2 * E_ * 4) return;
    int q  = idx & 3;
    int e2 = idx >> 2;
    int s, o, r;
    if (e2 < E_) { s = src[e2]; o = dst[e2]; r = rel[e2]; }
    else         { int e = e2 - E_; s = dst[e]; o = src[e]; r = rel[e] + R_; }
    float v = 1.0f / (float)g_cnt[r * N_ + s];
    const float4 w = *(const float4*)&g_w1[(size_t)r * NE_ + o * EMB_ + q * 4];
    float* hp = &g_h[s * EMB_ + q * 4];
    asm volatile("red.global.add.v4.f32 [%0], {%1, %2, %3, %4};"
                 :: "l"(hp), "f"(v * w.x), "f"(v * w.y), "f"(v * w.z), "f"(v * w.w)
                 : "memory");
}

// ---------------------------------------------------------------------------
// m[o][rc] = sum_e relu(h[o,e]+w1[40,o,e]+bias1[e]) * w2f[e][rc]
// w2 chunks in registers; h via shfl. ILP-2: two nodes per iteration,
// two independent shfl->FMA chains (fixes round-8 issue=38.8% latency bound).
__global__ void __launch_bounds__(192) k_mgemm(const float* __restrict__ bias1) {
    int w    = threadIdx.x >> 5;          // warp-class 0..5
    int lane = threadIdx.x & 31;
    int le   = lane & 15;
    int chunk = w * 32 + lane;
    bool act = chunk < CH_;
    int ch = act ? chunk : 0;

    float4 w2r[EMB_];
#pragma unroll
    for (int e = 0; e < EMB_; e++)
        w2r[e] = *(const float4*)&g_w2f[e * RC_ + ch * 4];
    float breg = bias1[le];
    const float* w1sl = &g_w1[(size_t)(RT_ - 1) * NE_];

    const int G = gridDim.x;
    int node = blockIdx.x;
    float h0 = 0.0f, h1 = 0.0f;
    if (node < N_)
        h0 = fmaxf(g_h[node * EMB_ + le] + w1sl[node * EMB_ + le] + breg, 0.0f);
    if (node + G < N_)
        h1 = fmaxf(g_h[(node + G) * EMB_ + le] + w1sl[(node + G) * EMB_ + le] + breg, 0.0f);

    for (; node < N_; node += 2 * G) {
        int n2 = node + 2 * G, n3 = node + 3 * G;
        float p0 = 0.0f, p1 = 0.0f;
        if (n2 < N_)
            p0 = fmaxf(g_h[n2 * EMB_ + le] + w1sl[n2 * EMB_ + le] + breg, 0.0f);
        if (n3 < N_)
            p1 = fmaxf(g_h[n3 * EMB_ + le] + w1sl[n3 * EMB_ + le] + breg, 0.0f);

        float4 a0 = make_float4(0.f, 0.f, 0.f, 0.f);
        float4 a1 = make_float4(0.f, 0.f, 0.f, 0.f);
#pragma unroll
        for (int e = 0; e < EMB_; e++) {
            float he0 = __shfl_sync(0xffffffffu, h0, e);
            float he1 = __shfl_sync(0xffffffffu, h1, e);
            a0.x = fmaf(he0, w2r[e].x, a0.x); a1.x = fmaf(he1, w2r[e].x, a1.x);
            a0.y = fmaf(he0, w2r[e].y, a0.y); a1.y = fmaf(he1, w2r[e].y, a1.y);
            a0.z = fmaf(he0, w2r[e].z, a0.z); a1.z = fmaf(he1, w2r[e].z, a1.z);
            a0.w = fmaf(he0, w2r[e].w, a0.w); a1.w = fmaf(he1, w2r[e].w, a1.w);
        }
        if (act) {
            *(float4*)&g_m[(size_t)node * RC_ + chunk * 4] = a0;
            if (node + G < N_)
                *(float4*)&g_m[(size_t)(node + G) * RC_ + chunk * 4] = a1;
        }
        h0 = p0; h1 = p1;
    }
}

// ---------------------------------------------------------------------------
// layer-2 edge pass incl. self-loop pseudo-edges: out[s,:] += v * m[o][r][:]
__global__ void k_l2e(const int* __restrict__ src, const int* __restrict__ dst,
                      const int* __restrict__ rel, float* __restrict__ out) {
    int idx = blockIdx.x * blockDim.x + threadIdx.x;
    if (idx >= (2 * E_ + N_) * 4) return;
    int q  = idx & 3;
    int e2 = idx >> 2;
    int s, o, r;
    float v;
    if (e2 < E_) {
        s = src[e2]; o = dst[e2]; r = rel[e2];
        v = 1.0f / (float)g_cnt[r * N_ + s];
    } else if (e2 < 2 * E_) {
        int e = e2 - E_;
        s = dst[e]; o = src[e]; r = rel[e] + R_;
        v = 1.0f / (float)g_cnt[r * N_ + s];
    } else {
        int n = e2 - 2 * E_;
        s = n; o = n; r = RT_ - 1; v = 1.0f;
    }
    const float4 w = *(const float4*)&g_m[(size_t)o * RC_ + r * 16 + q * 4];
    float* op = &out[s * C_ + q * 4];
    asm volatile("red.global.add.v4.f32 [%0], {%1, %2, %3, %4};"
                 :: "l"(op), "f"(v * w.x), "f"(v * w.y), "f"(v * w.z), "f"(v * w.w)
                 : "memory");
}

// ---------------------------------------------------------------------------
extern "C" void kernel_launch(void* const* d_in, const int* in_sizes, int n_in,
                              void* d_out, int out_size) {
    const int*   src    = (const int*)d_in[0];
    const int*   dst    = (const int*)d_in[1];
    const int*   rel    = (const int*)d_in[2];
    const float* comps1 = (const float*)d_in[3];
    const float* bases1 = (const float*)d_in[4];
    const float* comps2 = (const float*)d_in[5];
    const float* bases2 = (const float*)d_in[6];
    const float* bias1  = (const float*)d_in[7];
    const float* bias2  = (const float*)d_in[8];
    float* out = (float*)d_out;

    const int T = 256;
    k_pre   <<<(RT_ * N_ + T - 1) / T, T>>>(out, bias2, comps2, bases2);
    k_w1c   <<<WBn + CBn, T>>>(comps1, bases1, src, dst, rel);
    k_l1    <<<(2 * E_ * 4 + T - 1) / T, T>>>(src, dst, rel);
    k_mgemm <<<444, 192>>>(bias1);
    k_l2e   <<<((2 * E_ + N_) * 4 + T - 1) / T, T>>>(src, dst, rel, out);
}